// round 15
// baseline (speedup 1.0000x reference)
#include <cuda_runtime.h>
#include <cstdint>

#define D 128
#define TQ 128
#define TK 64
#define NTHREADS 128
#define NGLOBAL 100
#define LPRE 2048
#define SP 4            // key-dimension splits (flash-decoding style)
#define BMAX 2
#define SMAX 8192

#define QS_STRIDE 136   // ≡8 mod 32: conflict-free v2 fragment LDS
#define KS_STRIDE 136   // K view of shared KV buffer (v2 frags)
#define VS_STRIDE 132   // V view of shared KV buffer (scalar loads, ≡4 mod 32)

#define QS_OFF 0
#define KV_OFF (TQ * QS_STRIDE)                 // 17408
#define SMEM_FLOATS (KV_OFF + TK * KS_STRIDE)   // 26112 floats = 104.4 KB -> 2 CTAs/SM

typedef unsigned int u32;

// split-K scratch (static device globals: allocation-free)
__device__ float g_Op[(size_t)SP * BMAX * SMAX * D];   // unnormalized partial O
__device__ float g_Ml[SP * BMAX * SMAX];               // per-row running max (log2 domain)
__device__ float g_Ll[SP * BMAX * SMAX];               // per-row partial denom

// k-slot remap: slot tig <-> logical dim 2tig, slot tig+4 <-> 2tig+1 (consistent
// across A and B). Raw-layout vector fragment loads; QK C-frag is directly the
// PV A-frag.
__device__ __forceinline__ void mma_tf32(float c[4], u32 a0, u32 a1, u32 a2, u32 a3,
                                         u32 b0, u32 b1) {
    asm volatile(
        "mma.sync.aligned.m16n8k8.row.col.f32.tf32.tf32.f32 "
        "{%0,%1,%2,%3}, {%4,%5,%6,%7}, {%8,%9}, {%0,%1,%2,%3};"
        : "+f"(c[0]), "+f"(c[1]), "+f"(c[2]), "+f"(c[3])
        : "r"(a0), "r"(a1), "r"(a2), "r"(a3), "r"(b0), "r"(b1));
}

__device__ __forceinline__ void cp_async16(u32 dst_smem, const void* src) {
    asm volatile("cp.async.cg.shared.global [%0], [%1], 16;"
                 :: "r"(dst_smem), "l"(src));
}
__device__ __forceinline__ void cp_commit() {
    asm volatile("cp.async.commit_group;");
}
__device__ __forceinline__ void cp_wait_0() {
    asm volatile("cp.async.wait_group 0;");
}

// fast exp2 for x <= 0 (poly deg-6, rel err ~1e-5). Handles -1e30 sentinel -> ~0.
__device__ __forceinline__ float fexp2(float x) {
    x = fmaxf(x, -126.0f);
    int ni = __float2int_rd(x);
    float f = x - (float)ni;
    float p = 1.54035304e-4f;
    p = fmaf(p, f, 1.33335581e-3f);
    p = fmaf(p, f, 9.61812911e-3f);
    p = fmaf(p, f, 5.55041087e-2f);
    p = fmaf(p, f, 2.40226507e-1f);
    p = fmaf(p, f, 6.93147181e-1f);
    p = fmaf(p, f, 1.0f);
    return __int_as_float(__float_as_int(p) + (ni << 23));
}

__global__ void __launch_bounds__(NTHREADS, 2)
lminf_kernel(const float* __restrict__ Q, const float* __restrict__ K,
             const float* __restrict__ V, int S) {
    extern __shared__ float sm[];
    float* Qs = sm + QS_OFF;
    float* Kr = sm + KV_OFF;   // K view (stride 136)
    float* Vr = sm + KV_OFF;   // V view (stride 132), same buffer, phased

    const int b   = blockIdx.y;
    const int q0  = blockIdx.x * TQ;
    const int sp  = blockIdx.z;
    const int tid = threadIdx.x;
    const int w    = tid >> 5;
    const int lane = tid & 31;
    const int g    = lane >> 2;   // group id 0..7
    const int tig  = lane & 3;    // thread-in-group 0..3
    const int qb   = 32 * w;      // warp's q-row base (4 warps x 32 = 128)

    const float* Qg = Q + (size_t)b * S * D;
    const float* Kg = K + (size_t)b * S * D;
    const float* Vg = V + (size_t)b * S * D;

    const float QSC2  = 0.0883883476f * 1.44269504089f;  // 1/sqrt(128) * log2(e)
    const float LOG2E = 1.44269504089f;

    // ---- enumerate visited tiles & take this split's contiguous chunk ----
    const int nTile = (q0 + TQ) / TK;
    int tLoc = 2;
    {
        int dd = q0 - (LPRE - 1) - TK;   // tile t skipped iff t>=2 && 64t <= dd
        if (dd >= 0) { int t = dd / TK + 1; if (t > 2) tLoc = t; }
    }
    int NT = 2 + (nTile - tLoc);
    if (nTile < 2) NT = nTile;
    const int it0 = (sp * NT) / SP;
    const int it1 = ((sp + 1) * NT) / SP;

    const u32 smem_u32 = (u32)__cvta_generic_to_shared(sm);
    const u32 qbuf  = smem_u32 + QS_OFF * 4;
    const u32 kvbuf = smem_u32 + KV_OFF * 4;

    auto k0_of = [&](int it) { return ((it < 2) ? it : (tLoc + it - 2)) * TK; };

    auto load_k = [&](int it) {
        const float* ksrc = Kg + (size_t)k0_of(it) * D;
        #pragma unroll
        for (int c = 0; c < (TK * 32) / NTHREADS; c++) {
            int idx = tid + c * NTHREADS;
            int row = idx >> 5, c4 = idx & 31;
            cp_async16(kvbuf + (u32)(row * KS_STRIDE + c4 * 4) * 4, ksrc + row * D + c4 * 4);
        }
        cp_commit();
    };
    auto load_v = [&](int it) {
        const float* vsrc = Vg + (size_t)k0_of(it) * D;
        #pragma unroll
        for (int c = 0; c < (TK * 32) / NTHREADS; c++) {
            int idx = tid + c * NTHREADS;
            int row = idx >> 5, c4 = idx & 31;
            cp_async16(kvbuf + (u32)(row * VS_STRIDE + c4 * 4) * 4, vsrc + row * D + c4 * 4);
        }
        cp_commit();
    };

    if (it0 < it1) {
        // one group: Q + K(it0)
        const float* qsrc = Qg + (size_t)q0 * D;
        #pragma unroll
        for (int c = 0; c < (TQ * 32) / NTHREADS; c++) {
            int idx = tid + c * NTHREADS;
            int row = idx >> 5, c4 = idx & 31;
            cp_async16(qbuf + (u32)(row * QS_STRIDE + c4 * 4) * 4, qsrc + row * D + c4 * 4);
        }
        {
            const float* ksrc = Kg + (size_t)k0_of(it0) * D;
            #pragma unroll
            for (int c = 0; c < (TK * 32) / NTHREADS; c++) {
                int idx = tid + c * NTHREADS;
                int row = idx >> 5, c4 = idx & 31;
                cp_async16(kvbuf + (u32)(row * KS_STRIDE + c4 * 4) * 4, ksrc + row * D + c4 * 4);
            }
        }
        cp_commit();
    }

    // O accum: 2 q-subtiles x 16 dim-tiles x {r0d0,r0d1,r1d0,r1d1}
    float co[2][16][4];
    #pragma unroll
    for (int qt = 0; qt < 2; qt++)
        #pragma unroll
        for (int nt = 0; nt < 16; nt++)
            #pragma unroll
            for (int e = 0; e < 4; e++) co[qt][nt][e] = 0.0f;
    float mm[2][2], ll[2][2];
    #pragma unroll
    for (int qt = 0; qt < 2; qt++) { mm[qt][0] = mm[qt][1] = -1e30f; ll[qt][0] = ll[qt][1] = 0.0f; }

    // per-thread row indices: qt subtile rows (g, g+8) at base qb+16qt
    const int ir[2][2] = { { q0 + qb + g, q0 + qb + g + 8 },
                           { q0 + qb + 16 + g, q0 + qb + 24 + g } };

    for (int it = it0; it < it1; it++) {
        const int k0 = k0_of(it);

        cp_wait_0();               // K(it) resident (Q too on first iter)
        __syncthreads();

        // ---- QK^T: 32q x 64k per warp ----
        float c[2][8][4];
        #pragma unroll
        for (int qt = 0; qt < 2; qt++)
            #pragma unroll
            for (int nt = 0; nt < 8; nt++)
                #pragma unroll
                for (int e = 0; e < 4; e++) c[qt][nt][e] = 0.0f;

        #pragma unroll
        for (int kk = 0; kk < 16; kk++) {
            uint2 a00 = *(const uint2*)&Qs[(qb + g)      * QS_STRIDE + 8 * kk + 2 * tig];
            uint2 a01 = *(const uint2*)&Qs[(qb + g + 8)  * QS_STRIDE + 8 * kk + 2 * tig];
            uint2 a10 = *(const uint2*)&Qs[(qb + g + 16) * QS_STRIDE + 8 * kk + 2 * tig];
            uint2 a11 = *(const uint2*)&Qs[(qb + g + 24) * QS_STRIDE + 8 * kk + 2 * tig];
            #pragma unroll
            for (int nt = 0; nt < 8; nt++) {
                uint2 b01 = *(const uint2*)&Kr[(8 * nt + g) * KS_STRIDE + 8 * kk + 2 * tig];
                mma_tf32(c[0][nt], a00.x, a01.x, a00.y, a01.y, b01.x, b01.y);
                mma_tf32(c[1][nt], a10.x, a11.x, a10.y, a11.y, b01.x, b01.y);
            }
        }

        __syncthreads();               // all warps done reading K view
        load_v(it);                    // V into shared buffer; covered by softmax

        // ---- mask + bias + online softmax ----
        const bool interior =
            (k0 + TK <= q0) && ((k0 >= q0 + TQ - LPRE) || (k0 == 0));

        float mx[2][2] = { { -1e30f, -1e30f }, { -1e30f, -1e30f } };
        if (interior) {
            #pragma unroll
            for (int qt = 0; qt < 2; qt++) {
                const float bias0 = (float)(k0 - ir[qt][0]) * LOG2E;
                const float bias1 = (float)(k0 - ir[qt][1]) * LOG2E;
                #pragma unroll
                for (int nt = 0; nt < 8; nt++) {
                    float d0 = (float)(8 * nt + 2 * tig);
                    c[qt][nt][0] = fmaf(c[qt][nt][0], QSC2, fmaf(d0,        LOG2E, bias0));
                    c[qt][nt][1] = fmaf(c[qt][nt][1], QSC2, fmaf(d0 + 1.0f, LOG2E, bias0));
                    c[qt][nt][2] = fmaf(c[qt][nt][2], QSC2, fmaf(d0,        LOG2E, bias1));
                    c[qt][nt][3] = fmaf(c[qt][nt][3], QSC2, fmaf(d0 + 1.0f, LOG2E, bias1));
                    mx[qt][0] = fmaxf(mx[qt][0], fmaxf(c[qt][nt][0], c[qt][nt][1]));
                    mx[qt][1] = fmaxf(mx[qt][1], fmaxf(c[qt][nt][2], c[qt][nt][3]));
                }
            }
        } else {
            #pragma unroll
            for (int qt = 0; qt < 2; qt++) {
                const int i0 = ir[qt][0], i1 = ir[qt][1];
                #pragma unroll
                for (int nt = 0; nt < 8; nt++) {
                    int j0 = k0 + 8 * nt + 2 * tig;
                    int j1 = j0 + 1;
                    bool ok00 = (j0 <= i0) && ((j0 < NGLOBAL) || (j0 >= i0 - (LPRE - 1)));
                    bool ok01 = (j1 <= i0) && ((j1 < NGLOBAL) || (j1 >= i0 - (LPRE - 1)));
                    bool ok10 = (j0 <= i1) && ((j0 < NGLOBAL) || (j0 >= i1 - (LPRE - 1)));
                    bool ok11 = (j1 <= i1) && ((j1 < NGLOBAL) || (j1 >= i1 - (LPRE - 1)));
                    c[qt][nt][0] = ok00 ? fmaf(c[qt][nt][0], QSC2, (float)(j0 - i0) * LOG2E) : -1e30f;
                    c[qt][nt][1] = ok01 ? fmaf(c[qt][nt][1], QSC2, (float)(j1 - i0) * LOG2E) : -1e30f;
                    c[qt][nt][2] = ok10 ? fmaf(c[qt][nt][2], QSC2, (float)(j0 - i1) * LOG2E) : -1e30f;
                    c[qt][nt][3] = ok11 ? fmaf(c[qt][nt][3], QSC2, (float)(j1 - i1) * LOG2E) : -1e30f;
                    mx[qt][0] = fmaxf(mx[qt][0], fmaxf(c[qt][nt][0], c[qt][nt][1]));
                    mx[qt][1] = fmaxf(mx[qt][1], fmaxf(c[qt][nt][2], c[qt][nt][3]));
                }
            }
        }

        #pragma unroll
        for (int qt = 0; qt < 2; qt++) {
            #pragma unroll
            for (int h = 0; h < 2; h++) {
                float v = mx[qt][h];
                v = fmaxf(v, __shfl_xor_sync(0xffffffffu, v, 1));
                v = fmaxf(v, __shfl_xor_sync(0xffffffffu, v, 2));
                mx[qt][h] = v;
            }
            float mn0 = fmaxf(mm[qt][0], mx[qt][0]);
            float mn1 = fmaxf(mm[qt][1], mx[qt][1]);
            float sc0 = fexp2(mm[qt][0] - mn0);
            float sc1 = fexp2(mm[qt][1] - mn1);
            float ps0 = 0.0f, ps1 = 0.0f;
            #pragma unroll
            for (int nt = 0; nt < 8; nt++) {
                float p00 = fexp2(c[qt][nt][0] - mn0);
                float p01 = fexp2(c[qt][nt][1] - mn0);
                float p10 = fexp2(c[qt][nt][2] - mn1);
                float p11 = fexp2(c[qt][nt][3] - mn1);
                ps0 += p00 + p01;
                ps1 += p10 + p11;
                c[qt][nt][0] = p00; c[qt][nt][1] = p01;
                c[qt][nt][2] = p10; c[qt][nt][3] = p11;
            }
            ps0 += __shfl_xor_sync(0xffffffffu, ps0, 1);
            ps0 += __shfl_xor_sync(0xffffffffu, ps0, 2);
            ps1 += __shfl_xor_sync(0xffffffffu, ps1, 1);
            ps1 += __shfl_xor_sync(0xffffffffu, ps1, 2);
            ll[qt][0] = ll[qt][0] * sc0 + ps0;  mm[qt][0] = mn0;
            ll[qt][1] = ll[qt][1] * sc1 + ps1;  mm[qt][1] = mn1;
            #pragma unroll
            for (int nt = 0; nt < 16; nt++) {
                co[qt][nt][0] *= sc0; co[qt][nt][1] *= sc0;
                co[qt][nt][2] *= sc1; co[qt][nt][3] *= sc1;
            }
        }

        cp_wait_0();               // V(it) resident
        __syncthreads();

        // ---- P x V: C-frags are A-frags; each V frag feeds both q-subtiles ----
        #pragma unroll
        for (int kt = 0; kt < 8; kt++) {
            u32 a00 = __float_as_uint(c[0][kt][0]);
            u32 a01 = __float_as_uint(c[0][kt][2]);
            u32 a02 = __float_as_uint(c[0][kt][1]);
            u32 a03 = __float_as_uint(c[0][kt][3]);
            u32 a10 = __float_as_uint(c[1][kt][0]);
            u32 a11 = __float_as_uint(c[1][kt][2]);
            u32 a12 = __float_as_uint(c[1][kt][1]);
            u32 a13 = __float_as_uint(c[1][kt][3]);
            const float* vrow = Vr + (8 * kt + 2 * tig) * VS_STRIDE + g;
            #pragma unroll
            for (int nt = 0; nt < 16; nt++) {
                u32 b0 = __float_as_uint(vrow[8 * nt]);
                u32 b1 = __float_as_uint(vrow[VS_STRIDE + 8 * nt]);
                mma_tf32(co[0][nt], a00, a01, a02, a03, b0, b1);
                mma_tf32(co[1][nt], a10, a11, a12, a13, b0, b1);
            }
        }

        __syncthreads();                    // V reads done; buffer free
        if (it + 1 < it1) load_k(it + 1);   // refill K (exposed ~600cyc, ~5%)
    }

    // ---- epilogue: write unnormalized partials for this split ----
    const size_t rowbase = (size_t)(sp * BMAX + b) * S;
    #pragma unroll
    for (int qt = 0; qt < 2; qt++) {
        float2* o0 = (float2*)(g_Op + (rowbase + ir[qt][0]) * D);
        float2* o1 = (float2*)(g_Op + (rowbase + ir[qt][1]) * D);
        #pragma unroll
        for (int nt = 0; nt < 16; nt++) {
            o0[4 * nt + tig] = make_float2(co[qt][nt][0], co[qt][nt][1]);
            o1[4 * nt + tig] = make_float2(co[qt][nt][2], co[qt][nt][3]);
        }
        if (tig == 0) {
            g_Ml[rowbase + ir[qt][0]] = mm[qt][0];  g_Ll[rowbase + ir[qt][0]] = ll[qt][0];
            g_Ml[rowbase + ir[qt][1]] = mm[qt][1];  g_Ll[rowbase + ir[qt][1]] = ll[qt][1];
        }
    }
}

__global__ void __launch_bounds__(256)
combine_kernel(float* __restrict__ O, int S) {
    const int d4pr  = D / 4;                       // float4 per row
    const int total = BMAX * S * d4pr;             // float4 units
    int idx = blockIdx.x * blockDim.x + threadIdx.x;
    if (idx >= total) return;
    int row = idx / d4pr;                          // b*S + i

    const size_t rstride = (size_t)BMAX * S;
    float ms[SP], ls[SP];
    float m = -1e30f;
    #pragma unroll
    for (int s = 0; s < SP; s++) {
        ms[s] = g_Ml[s * rstride + row];
        ls[s] = g_Ll[s * rstride + row];
        if (ls[s] > 0.0f) m = fmaxf(m, ms[s]);
    }
    const float4* Op4 = (const float4*)g_Op;
    float denom = 0.0f;
    float4 acc = make_float4(0.0f, 0.0f, 0.0f, 0.0f);
    #pragma unroll
    for (int s = 0; s < SP; s++) {
        if (ls[s] > 0.0f) {
            float wv = fexp2(ms[s] - m);
            denom = fmaf(wv, ls[s], denom);
            float4 o = Op4[(size_t)s * total + idx];
            acc.x = fmaf(wv, o.x, acc.x);
            acc.y = fmaf(wv, o.y, acc.y);
            acc.z = fmaf(wv, o.z, acc.z);
            acc.w = fmaf(wv, o.w, acc.w);
        }
    }
    float inv = 1.0f / denom;
    ((float4*)O)[idx] = make_float4(acc.x * inv, acc.y * inv, acc.z * inv, acc.w * inv);
}

extern "C" void kernel_launch(void* const* d_in, const int* in_sizes, int n_in,
                              void* d_out, int out_size) {
    const float* q = (const float*)d_in[0];
    const float* k = (const float*)d_in[1];
    const float* v = (const float*)d_in[2];
    float* o = (float*)d_out;

    const int B = 2;
    const int S = in_sizes[0] / (B * D);   // 8192

    size_t smem_bytes = (size_t)SMEM_FLOATS * sizeof(float);  // 104.4 KB -> 2 CTAs/SM
    cudaFuncSetAttribute(lminf_kernel, cudaFuncAttributeMaxDynamicSharedMemorySize,
                         (int)smem_bytes);

    dim3 grid(S / TQ, B, SP);
    lminf_kernel<<<grid, NTHREADS, smem_bytes>>>(q, k, v, S);

    int total4 = B * S * (D / 4);
    combine_kernel<<<(total4 + 255) / 256, 256>>>(o, S);
}

// round 16
// speedup vs baseline: 1.2114x; 1.2114x over previous
#include <cuda_runtime.h>
#include <cstdint>

#define D 128
#define TQ 64
#define TK 64
#define NTHREADS 128
#define NGLOBAL 100
#define LPRE 2048
#define SP 4            // key-dimension splits (flash-decoding style)
#define BMAX 2
#define SMAX 8192

#define QS_STRIDE 136   // ≡8 mod 32: conflict-free v2 fragment LDS
#define KS_STRIDE 136   // ≡8 mod 32: conflict-free v2 fragment LDS
#define VS_STRIDE 132   // ≡4 mod 32: conflict-free scalar V loads (rows 2tig, +1)

#define QS_OFF 0
#define K0_OFF (TQ * QS_STRIDE)            // 8704
#define V0_OFF (K0_OFF + TK * KS_STRIDE)   // 17408
#define SMEM_FLOATS (V0_OFF + TK * VS_STRIDE)   // 25856 floats = 103.4 KB -> 2 CTAs/SM

typedef unsigned int u32;

// split-K scratch (static device globals: allocation-free)
__device__ float g_Op[(size_t)SP * BMAX * SMAX * D];   // unnormalized partial O
__device__ float g_Ml[SP * BMAX * SMAX];               // per-row running max (log2 domain)
__device__ float g_Ll[SP * BMAX * SMAX];               // per-row partial denom

// k-slot remap: slot tig <-> logical dim 2tig, slot tig+4 <-> 2tig+1 (consistent
// across A and B, so the MMA contraction is unchanged). Raw-layout vector frags;
// QK C-frag is directly the PV A-frag.
__device__ __forceinline__ void mma_tf32(float c[4], u32 a0, u32 a1, u32 a2, u32 a3,
                                         u32 b0, u32 b1) {
    asm volatile(
        "mma.sync.aligned.m16n8k8.row.col.f32.tf32.tf32.f32 "
        "{%0,%1,%2,%3}, {%4,%5,%6,%7}, {%8,%9}, {%0,%1,%2,%3};"
        : "+f"(c[0]), "+f"(c[1]), "+f"(c[2]), "+f"(c[3])
        : "r"(a0), "r"(a1), "r"(a2), "r"(a3), "r"(b0), "r"(b1));
}

__device__ __forceinline__ void cp_async16(u32 dst_smem, const void* src) {
    asm volatile("cp.async.cg.shared.global [%0], [%1], 16;"
                 :: "r"(dst_smem), "l"(src));
}
__device__ __forceinline__ void cp_commit() {
    asm volatile("cp.async.commit_group;");
}
__device__ __forceinline__ void cp_wait_1() {   // allow 1 group outstanding
    asm volatile("cp.async.wait_group 1;");
}
__device__ __forceinline__ void cp_wait_0() {   // all groups done
    asm volatile("cp.async.wait_group 0;");
}

// fast exp2 for x <= 0 (poly deg-6, rel err ~1e-5). Handles -1e30 sentinel -> ~0.
__device__ __forceinline__ float fexp2(float x) {
    x = fmaxf(x, -126.0f);
    int ni = __float2int_rd(x);
    float f = x - (float)ni;
    float p = 1.54035304e-4f;
    p = fmaf(p, f, 1.33335581e-3f);
    p = fmaf(p, f, 9.61812911e-3f);
    p = fmaf(p, f, 5.55041087e-2f);
    p = fmaf(p, f, 2.40226507e-1f);
    p = fmaf(p, f, 6.93147181e-1f);
    p = fmaf(p, f, 1.0f);
    return __int_as_float(__float_as_int(p) + (ni << 23));
}

__global__ void __launch_bounds__(NTHREADS, 2)
lminf_kernel(const float* __restrict__ Q, const float* __restrict__ K,
             const float* __restrict__ V, int S) {
    extern __shared__ float sm[];
    float* Qs = sm + QS_OFF;
    float* Kr = sm + K0_OFF;
    float* Vr = sm + V0_OFF;

    const int b   = blockIdx.y;
    const int q0  = blockIdx.x * TQ;
    const int sp  = blockIdx.z;
    const int tid = threadIdx.x;
    const int w    = tid >> 5;
    const int lane = tid & 31;
    const int g    = lane >> 2;   // group id 0..7
    const int tig  = lane & 3;    // thread-in-group 0..3
    const int qb   = 16 * w;      // warp's q-row base within tile (4 warps x 16 = 64)

    const float* Qg = Q + (size_t)b * S * D;
    const float* Kg = K + (size_t)b * S * D;
    const float* Vg = V + (size_t)b * S * D;

    const float QSC2  = 0.0883883476f * 1.44269504089f;  // 1/sqrt(128) * log2(e)
    const float LOG2E = 1.44269504089f;

    // ---- enumerate visited tiles & take this split's contiguous chunk ----
    // visited = {0,1} (global sinks) ∪ [tLoc, nTile)
    const int nTile = (q0 + TQ) / TK;
    int tLoc = 2;
    {
        int dd = q0 - (LPRE - 1) - TK;   // tile t skipped iff t>=2 && 64t <= dd
        if (dd >= 0) { int t = dd / TK + 1; if (t > 2) tLoc = t; }
    }
    int NT = 2 + (nTile - tLoc);
    if (nTile < 2) NT = nTile;           // tiny q0: only causal tiles exist
    const int it0 = (sp * NT) / SP;
    const int it1 = ((sp + 1) * NT) / SP;

    const u32 smem_u32 = (u32)__cvta_generic_to_shared(sm);
    const u32 qbuf = smem_u32 + QS_OFF * 4;
    const u32 kbuf = smem_u32 + K0_OFF * 4;
    const u32 vbuf = smem_u32 + V0_OFF * 4;

    auto k0_of = [&](int it) { return ((it < 2) ? it : (tLoc + it - 2)) * TK; };

    // separate K / V loads, each its own commit group
    auto load_k = [&](int it) {
        const float* ksrc = Kg + (size_t)k0_of(it) * D;
        #pragma unroll
        for (int c = 0; c < (TK * 32) / NTHREADS; c++) {
            int idx = tid + c * NTHREADS;
            int row = idx >> 5, c4 = idx & 31;
            cp_async16(kbuf + (u32)(row * KS_STRIDE + c4 * 4) * 4, ksrc + row * D + c4 * 4);
        }
        cp_commit();
    };
    auto load_v = [&](int it) {
        const float* vsrc = Vg + (size_t)k0_of(it) * D;
        #pragma unroll
        for (int c = 0; c < (TK * 32) / NTHREADS; c++) {
            int idx = tid + c * NTHREADS;
            int row = idx >> 5, c4 = idx & 31;
            cp_async16(vbuf + (u32)(row * VS_STRIDE + c4 * 4) * 4, vsrc + row * D + c4 * 4);
        }
        cp_commit();
    };

    // Q fragments live in registers for the whole tile loop (invariant).
    u32 qf[16][4];

    if (it0 < it1) {
        // group 1: Q + K(it0); group 2: V(it0)
        const float* qsrc = Qg + (size_t)q0 * D;
        #pragma unroll
        for (int c = 0; c < (TQ * 32) / NTHREADS; c++) {
            int idx = tid + c * NTHREADS;
            int row = idx >> 5, c4 = idx & 31;
            cp_async16(qbuf + (u32)(row * QS_STRIDE + c4 * 4) * 4, qsrc + row * D + c4 * 4);
        }
        {
            const float* ksrc = Kg + (size_t)k0_of(it0) * D;
            #pragma unroll
            for (int c = 0; c < (TK * 32) / NTHREADS; c++) {
                int idx = tid + c * NTHREADS;
                int row = idx >> 5, c4 = idx & 31;
                cp_async16(kbuf + (u32)(row * KS_STRIDE + c4 * 4) * 4, ksrc + row * D + c4 * 4);
            }
        }
        cp_commit();
        load_v(it0);

        // retire group 1 (Q + first K) and hoist Q fragments to registers
        cp_wait_1();
        __syncthreads();
        #pragma unroll
        for (int kk = 0; kk < 16; kk++) {
            uint2 a02 = *(const uint2*)&Qs[(qb + g)     * QS_STRIDE + 8 * kk + 2 * tig];
            uint2 a13 = *(const uint2*)&Qs[(qb + g + 8) * QS_STRIDE + 8 * kk + 2 * tig];
            qf[kk][0] = a02.x; qf[kk][1] = a13.x;
            qf[kk][2] = a02.y; qf[kk][3] = a13.y;
        }
    }

    float co[16][4];              // O accum: 16 dim-tiles x {r0d0,r0d1,r1d0,r1d1}
    #pragma unroll
    for (int nt = 0; nt < 16; nt++)
        #pragma unroll
        for (int e = 0; e < 4; e++) co[nt][e] = 0.0f;
    float m0 = -1e30f, m1 = -1e30f, l0 = 0.0f, l1 = 0.0f;

    const int i0 = q0 + qb + g;
    const int i1 = i0 + 8;

    for (int it = it0; it < it1; it++) {
        const int k0 = k0_of(it);

        // pending at top: {K(it) [already retired on first iter], V(it)} ->
        // wait(1) guarantees K(it) resident
        cp_wait_1();
        __syncthreads();

        // ---- QK^T: 16x64 per warp; Q frags from registers, K raw v2 LDS ----
        float c[8][4];
        #pragma unroll
        for (int nt = 0; nt < 8; nt++)
            #pragma unroll
            for (int e = 0; e < 4; e++) c[nt][e] = 0.0f;

        #pragma unroll
        for (int kk = 0; kk < 16; kk++) {
            #pragma unroll
            for (int nt = 0; nt < 8; nt++) {
                uint2 b01 = *(const uint2*)&Kr[(8 * nt + g) * KS_STRIDE + 8 * kk + 2 * tig];
                mma_tf32(c[nt], qf[kk][0], qf[kk][1], qf[kk][2], qf[kk][3], b01.x, b01.y);
            }
        }

        __syncthreads();                    // all warps done reading Kr
        if (it + 1 < it1) load_k(it + 1);   // refill K; covered by softmax+PV

        // ---- mask + bias + online softmax ----
        // interior tile (fully allowed): causal strictly below diagonal AND
        // (inside local window for all rows, or the all-global tile k0==0)
        const bool interior =
            (k0 + TK <= q0) && ((k0 >= q0 + TQ - LPRE) || (k0 == 0));

        float mx0 = -1e30f, mx1 = -1e30f;
        if (interior) {
            const float bias00 = (float)(k0 - i0) * LOG2E;   // + (8nt+2tig+e)*LOG2E
            const float bias1  = (float)(k0 - i1) * LOG2E;
            #pragma unroll
            for (int nt = 0; nt < 8; nt++) {
                float d0 = (float)(8 * nt + 2 * tig);
                c[nt][0] = fmaf(c[nt][0], QSC2, fmaf(d0,        LOG2E, bias00));
                c[nt][1] = fmaf(c[nt][1], QSC2, fmaf(d0 + 1.0f, LOG2E, bias00));
                c[nt][2] = fmaf(c[nt][2], QSC2, fmaf(d0,        LOG2E, bias1));
                c[nt][3] = fmaf(c[nt][3], QSC2, fmaf(d0 + 1.0f, LOG2E, bias1));
                mx0 = fmaxf(mx0, fmaxf(c[nt][0], c[nt][1]));
                mx1 = fmaxf(mx1, fmaxf(c[nt][2], c[nt][3]));
            }
        } else {
            #pragma unroll
            for (int nt = 0; nt < 8; nt++) {
                int j0 = k0 + 8 * nt + 2 * tig;
                int j1 = j0 + 1;
                bool ok00 = (j0 <= i0) && ((j0 < NGLOBAL) || (j0 >= i0 - (LPRE - 1)));
                bool ok01 = (j1 <= i0) && ((j1 < NGLOBAL) || (j1 >= i0 - (LPRE - 1)));
                bool ok10 = (j0 <= i1) && ((j0 < NGLOBAL) || (j0 >= i1 - (LPRE - 1)));
                bool ok11 = (j1 <= i1) && ((j1 < NGLOBAL) || (j1 >= i1 - (LPRE - 1)));
                c[nt][0] = ok00 ? fmaf(c[nt][0], QSC2, (float)(j0 - i0) * LOG2E) : -1e30f;
                c[nt][1] = ok01 ? fmaf(c[nt][1], QSC2, (float)(j1 - i0) * LOG2E) : -1e30f;
                c[nt][2] = ok10 ? fmaf(c[nt][2], QSC2, (float)(j0 - i1) * LOG2E) : -1e30f;
                c[nt][3] = ok11 ? fmaf(c[nt][3], QSC2, (float)(j1 - i1) * LOG2E) : -1e30f;
                mx0 = fmaxf(mx0, fmaxf(c[nt][0], c[nt][1]));
                mx1 = fmaxf(mx1, fmaxf(c[nt][2], c[nt][3]));
            }
        }
        mx0 = fmaxf(mx0, __shfl_xor_sync(0xffffffffu, mx0, 1));
        mx0 = fmaxf(mx0, __shfl_xor_sync(0xffffffffu, mx0, 2));
        mx1 = fmaxf(mx1, __shfl_xor_sync(0xffffffffu, mx1, 1));
        mx1 = fmaxf(mx1, __shfl_xor_sync(0xffffffffu, mx1, 2));

        float mn0 = fmaxf(m0, mx0), mn1 = fmaxf(m1, mx1);
        float sc0 = fexp2(m0 - mn0), sc1 = fexp2(m1 - mn1);
        float ps0 = 0.0f, ps1 = 0.0f;
        #pragma unroll
        for (int nt = 0; nt < 8; nt++) {
            float p00 = fexp2(c[nt][0] - mn0);
            float p01 = fexp2(c[nt][1] - mn0);
            float p10 = fexp2(c[nt][2] - mn1);
            float p11 = fexp2(c[nt][3] - mn1);
            ps0 += p00 + p01;
            ps1 += p10 + p11;
            c[nt][0] = p00; c[nt][1] = p01; c[nt][2] = p10; c[nt][3] = p11;
        }
        ps0 += __shfl_xor_sync(0xffffffffu, ps0, 1);
        ps0 += __shfl_xor_sync(0xffffffffu, ps0, 2);
        ps1 += __shfl_xor_sync(0xffffffffu, ps1, 1);
        ps1 += __shfl_xor_sync(0xffffffffu, ps1, 2);

        l0 = l0 * sc0 + ps0;  m0 = mn0;
        l1 = l1 * sc1 + ps1;  m1 = mn1;
        #pragma unroll
        for (int nt = 0; nt < 16; nt++) {
            co[nt][0] *= sc0; co[nt][1] *= sc0;
            co[nt][2] *= sc1; co[nt][3] *= sc1;
        }

        // V(it) arrival: pending {V(it), K(it+1)} -> wait(1); last iter: wait(0)
        if (it + 1 < it1) cp_wait_1(); else cp_wait_0();
        __syncthreads();

        // ---- P x V: C-frag IS the A-frag under the k-slot remap (no shuffles) ----
        #pragma unroll
        for (int kt = 0; kt < 8; kt++) {
            u32 a0 = __float_as_uint(c[kt][0]);   // row g,   slot tig   (= logical 2tig)
            u32 a1 = __float_as_uint(c[kt][2]);   // row g+8, slot tig
            u32 a2 = __float_as_uint(c[kt][1]);   // row g,   slot tig+4 (= logical 2tig+1)
            u32 a3 = __float_as_uint(c[kt][3]);   // row g+8, slot tig+4
            const float* vrow = Vr + (8 * kt + 2 * tig) * VS_STRIDE + g;
            #pragma unroll
            for (int nt = 0; nt < 16; nt++) {
                u32 b0 = __float_as_uint(vrow[8 * nt]);              // V[2tig][d]
                u32 b1 = __float_as_uint(vrow[VS_STRIDE + 8 * nt]);  // V[2tig+1][d]
                mma_tf32(co[nt], a0, a1, a2, a3, b0, b1);
            }
        }

        __syncthreads();                    // all warps done reading Vr
        if (it + 1 < it1) load_v(it + 1);   // refill V; covered by next QK+softmax
    }

    // ---- epilogue: write unnormalized partials for this split ----
    const size_t rowbase = (size_t)(sp * BMAX + b) * S;
    float2* o0 = (float2*)(g_Op + (rowbase + i0) * D);
    float2* o1 = (float2*)(g_Op + (rowbase + i1) * D);
    #pragma unroll
    for (int nt = 0; nt < 16; nt++) {
        o0[4 * nt + tig] = make_float2(co[nt][0], co[nt][1]);
        o1[4 * nt + tig] = make_float2(co[nt][2], co[nt][3]);
    }
    if (tig == 0) {
        g_Ml[rowbase + i0] = m0;  g_Ll[rowbase + i0] = l0;
        g_Ml[rowbase + i1] = m1;  g_Ll[rowbase + i1] = l1;
    }
}

__global__ void __launch_bounds__(256)
combine_kernel(float* __restrict__ O, int S) {
    const int d4pr  = D / 4;                       // float4 per row
    const int total = BMAX * S * d4pr;             // float4 units
    int idx = blockIdx.x * blockDim.x + threadIdx.x;
    if (idx >= total) return;
    int row = idx / d4pr;                          // b*S + i

    const size_t rstride = (size_t)BMAX * S;
    float ms[SP], ls[SP];
    float m = -1e30f;
    #pragma unroll
    for (int s = 0; s < SP; s++) {
        ms[s] = g_Ml[s * rstride + row];
        ls[s] = g_Ll[s * rstride + row];
        if (ls[s] > 0.0f) m = fmaxf(m, ms[s]);
    }
    const float4* Op4 = (const float4*)g_Op;
    float denom = 0.0f;
    float4 acc = make_float4(0.0f, 0.0f, 0.0f, 0.0f);
    #pragma unroll
    for (int s = 0; s < SP; s++) {
        if (ls[s] > 0.0f) {
            float wv = fexp2(ms[s] - m);
            denom = fmaf(wv, ls[s], denom);
            float4 o = Op4[(size_t)s * total + idx];
            acc.x = fmaf(wv, o.x, acc.x);
            acc.y = fmaf(wv, o.y, acc.y);
            acc.z = fmaf(wv, o.z, acc.z);
            acc.w = fmaf(wv, o.w, acc.w);
        }
    }
    float inv = 1.0f / denom;
    ((float4*)O)[idx] = make_float4(acc.x * inv, acc.y * inv, acc.z * inv, acc.w * inv);
}

extern "C" void kernel_launch(void* const* d_in, const int* in_sizes, int n_in,
                              void* d_out, int out_size) {
    const float* q = (const float*)d_in[0];
    const float* k = (const float*)d_in[1];
    const float* v = (const float*)d_in[2];
    float* o = (float*)d_out;

    const int B = 2;
    const int S = in_sizes[0] / (B * D);   // 8192

    size_t smem_bytes = (size_t)SMEM_FLOATS * sizeof(float);  // 103.4 KB -> 2 CTAs/SM
    cudaFuncSetAttribute(lminf_kernel, cudaFuncAttributeMaxDynamicSharedMemorySize,
                         (int)smem_bytes);

    dim3 grid(S / TQ, B, SP);
    lminf_kernel<<<grid, NTHREADS, smem_bytes>>>(q, k, v, S);

    int total4 = B * S * (D / 4);
    combine_kernel<<<(total4 + 255) / 256, 256>>>(o, S);
}